// round 14
// baseline (speedup 1.0000x reference)
#include <cuda_runtime.h>

// ScatterLoss — R13 + phase-2 critical-path cuts:
//   counts via phase-1 smem histogram (no y re-scan),
//   S_tot and sumsq replicated x4 (chain 128 -> 32).
//   loss = (||S_tot||^2 - sum_c ||S_c||^2) / (N^2 - sum_c n_c^2)

#define D_DIM 256
#define C_PAD 128      // labels in [0,100)
#define NTHR  1024     // 32 warps/CTA, 2 rows/warp -> 64 rows/CTA
#define KREP  4
#define SLAB  (C_PAD * D_DIM)

__device__ float    g_csum[KREP * SLAB];   // zeroed at load; re-zeroed by owners
__device__ int      g_ccnt[C_PAD];
__device__ float    g_Stot[KREP][D_DIM];
__device__ float    g_sumsq[KREP];
__device__ int      g_cnt2;
__device__ unsigned g_bar;
__device__ unsigned g_done;

__device__ __forceinline__ void red_v4(float* p, float x, float y, float z, float w) {
    asm volatile("red.global.add.v4.f32 [%0], {%1, %2, %3, %4};"
                 :: "l"(p), "f"(x), "f"(y), "f"(z), "f"(w) : "memory");
}

__global__ __launch_bounds__(NTHR, 1)
void fused_k(const float* __restrict__ e, const int* __restrict__ y,
             int N, float* __restrict__ out) {
    const int tid  = threadIdx.x;
    const int lane = tid & 31;
    const int w    = (blockIdx.x * NTHR + tid) >> 5;
    float* csum = g_csum + (blockIdx.x & (KREP - 1)) * SLAB;

    __shared__ int s_hist[C_PAD];
    if (tid < C_PAD) s_hist[tid] = 0;
    __syncthreads();

    // ---- Phase 1: warp w handles rows 2w, 2w+1 ------------------------------
    const int r0 = 2 * w, r1 = 2 * w + 1;
    if (r0 < N) {
        const bool has1 = (r1 < N);
        int c0 = y[r0];
        int c1 = has1 ? y[r1] : -1;

        const float4* e0 = (const float4*)(e + (size_t)r0 * D_DIM);
        const float4* e1 = (const float4*)(e + (size_t)r1 * D_DIM);
        float4 a0 = e0[lane];
        float4 b0 = e0[lane + 32];
        float4 a1, b1;
        if (has1) { a1 = e1[lane]; b1 = e1[lane + 32]; }
        else      { a1 = make_float4(0,0,0,0); b1 = a1; }

        float s0 = a0.x*a0.x + a0.y*a0.y + a0.z*a0.z + a0.w*a0.w
                 + b0.x*b0.x + b0.y*b0.y + b0.z*b0.z + b0.w*b0.w;
        float s1 = a1.x*a1.x + a1.y*a1.y + a1.z*a1.z + a1.w*a1.w
                 + b1.x*b1.x + b1.y*b1.y + b1.z*b1.z + b1.w*b1.w;
        #pragma unroll
        for (int o = 16; o > 0; o >>= 1) {
            s0 += __shfl_xor_sync(0xffffffffu, s0, o);
            s1 += __shfl_xor_sync(0xffffffffu, s1, o);
        }
        float q0 = rsqrtf(s0);
        float q1 = rsqrtf(s1);

        if ((unsigned)c0 < C_PAD) {
            float* d0 = csum + c0 * D_DIM + lane * 4;
            red_v4(d0,       a0.x*q0, a0.y*q0, a0.z*q0, a0.w*q0);
            red_v4(d0 + 128, b0.x*q0, b0.y*q0, b0.z*q0, b0.w*q0);
            if (lane == 0) atomicAdd(&s_hist[c0], 1);      // smem, cheap
        }
        if ((unsigned)c1 < C_PAD) {
            float* d1 = csum + c1 * D_DIM + lane * 4;
            red_v4(d1,       a1.x*q1, a1.y*q1, a1.z*q1, a1.w*q1);
            red_v4(d1 + 128, b1.x*q1, b1.y*q1, b1.z*q1, b1.w*q1);
            if (lane == 1) atomicAdd(&s_hist[c1], 1);
        }
    }
    __syncthreads();
    if (tid < C_PAD) {
        int h = s_hist[tid];
        if (h) atomicAdd(&g_ccnt[tid], h);   // drains alongside f32 reds
    }

    // ---- Grid spin barrier (all CTAs co-resident: grid <= 128) --------------
    __threadfence();
    __syncthreads();
    if (tid == 0) {
        atomicAdd(&g_bar, 1u);
        unsigned v;
        do {
            asm volatile("ld.acquire.gpu.u32 %0, [%1];" : "=r"(v) : "l"(&g_bar));
            if (v >= gridDim.x) break;
            __nanosleep(32);
        } while (1);
    }
    __syncthreads();

    // ---- Phase 2: CTA c owns class c ----------------------------------------
    __shared__ float s_S[D_DIM];
    __shared__ float s_part[8];

    for (int c = blockIdx.x; c < C_PAD; c += gridDim.x) {
        float t = 0.0f;
        if (tid < D_DIM) {
            float v0 = __ldcg(&g_csum[0*SLAB + c * D_DIM + tid]);
            float v1 = __ldcg(&g_csum[1*SLAB + c * D_DIM + tid]);
            float v2 = __ldcg(&g_csum[2*SLAB + c * D_DIM + tid]);
            float v3 = __ldcg(&g_csum[3*SLAB + c * D_DIM + tid]);
            t = (v0 + v1) + (v2 + v3);
            s_S[tid] = t;
        }
        float v = t * t;
        #pragma unroll
        for (int o = 16; o > 0; o >>= 1)
            v += __shfl_xor_sync(0xffffffffu, v, o);
        if (tid < D_DIM && lane == 0) s_part[tid >> 5] = v;
        __syncthreads();

        if (tid < 64)   // fold S_c into replicated S_tot (chain 32, not 128)
            red_v4(&g_Stot[c & (KREP-1)][tid * 4],
                   s_S[4*tid], s_S[4*tid+1], s_S[4*tid+2], s_S[4*tid+3]);
        if (tid == 0) {
            float ssq = s_part[0] + s_part[1] + s_part[2] + s_part[3]
                      + s_part[4] + s_part[5] + s_part[6] + s_part[7];
            atomicAdd(&g_sumsq[c & (KREP-1)], ssq);
            int n = __ldcg(&g_ccnt[c]);
            atomicAdd(&g_cnt2, n * n);
            g_ccnt[c] = 0;                      // reset for next replay
        }
        // zero own rows (all replicas) for next replay
        if (tid < 64) {
            const float4 z4 = make_float4(0.f,0.f,0.f,0.f);
            ((float4*)(g_csum + 0*SLAB + c * D_DIM))[tid] = z4;
            ((float4*)(g_csum + 1*SLAB + c * D_DIM))[tid] = z4;
            ((float4*)(g_csum + 2*SLAB + c * D_DIM))[tid] = z4;
            ((float4*)(g_csum + 3*SLAB + c * D_DIM))[tid] = z4;
        }
        __syncthreads();
    }

    // ---- Arrive; last CTA finalizes -----------------------------------------
    __shared__ unsigned s_rank;
    __threadfence();
    __syncthreads();
    if (tid == 0) s_rank = atomicAdd(&g_done, 1u);
    __syncthreads();
    if (s_rank != gridDim.x - 1) return;

    float t2 = 0.0f;
    if (tid < D_DIM) {
        float tt = __ldcg(&g_Stot[0][tid]) + __ldcg(&g_Stot[1][tid])
                 + __ldcg(&g_Stot[2][tid]) + __ldcg(&g_Stot[3][tid]);
        t2 = tt * tt;
        g_Stot[0][tid] = 0.f; g_Stot[1][tid] = 0.f;
        g_Stot[2][tid] = 0.f; g_Stot[3][tid] = 0.f;
    }
    #pragma unroll
    for (int o = 16; o > 0; o >>= 1)
        t2 += __shfl_xor_sync(0xffffffffu, t2, o);
    if (tid < D_DIM && lane == 0) s_part[tid >> 5] = t2;
    __syncthreads();

    if (tid == 0) {
        float tot2 = s_part[0] + s_part[1] + s_part[2] + s_part[3]
                   + s_part[4] + s_part[5] + s_part[6] + s_part[7];
        float ssum = __ldcg(&g_sumsq[0]) + __ldcg(&g_sumsq[1])
                   + __ldcg(&g_sumsq[2]) + __ldcg(&g_sumsq[3]);
        double num = (double)tot2 - (double)ssum;
        double den = (double)N * (double)N - (double)__ldcg(&g_cnt2);
        out[0] = (float)(num / den);
        g_sumsq[0] = 0.f; g_sumsq[1] = 0.f; g_sumsq[2] = 0.f; g_sumsq[3] = 0.f;
        g_cnt2 = 0;
        g_bar  = 0;
        g_done = 0;
    }
}

extern "C" void kernel_launch(void* const* d_in, const int* in_sizes, int n_in,
                              void* d_out, int out_size) {
    const float* e   = (const float*)d_in[0];
    const int*   y   = (const int*)d_in[1];
    float*       out = (float*)d_out;
    int N = in_sizes[1];

    // all CTAs co-resident for the spin barrier
    int nblk = (N + 63) / 64;
    if (nblk > 128) nblk = 128;
    if (nblk < 1)   nblk = 1;
    fused_k<<<nblk, NTHR>>>(e, y, N, out);
}

// round 15
// speedup vs baseline: 1.0494x; 1.0494x over previous
#include <cuda_runtime.h>

// ScatterLoss — R14 + per-warp column rotation (de-phases per-sector red
// bursts) + tight barrier spin.
//   loss = (||S_tot||^2 - sum_c ||S_c||^2) / (N^2 - sum_c n_c^2)

#define D_DIM 256
#define C_PAD 128      // labels in [0,100)
#define NTHR  1024     // 32 warps/CTA, 2 rows/warp -> 64 rows/CTA
#define KREP  4
#define SLAB  (C_PAD * D_DIM)

__device__ float    g_csum[KREP * SLAB];   // zeroed at load; re-zeroed by owners
__device__ int      g_ccnt[C_PAD];
__device__ float    g_Stot[KREP][D_DIM];
__device__ float    g_sumsq[KREP];
__device__ int      g_cnt2;
__device__ unsigned g_bar;
__device__ unsigned g_done;

__device__ __forceinline__ void red_v4(float* p, float x, float y, float z, float w) {
    asm volatile("red.global.add.v4.f32 [%0], {%1, %2, %3, %4};"
                 :: "l"(p), "f"(x), "f"(y), "f"(z), "f"(w) : "memory");
}

__global__ __launch_bounds__(NTHR, 1)
void fused_k(const float* __restrict__ e, const int* __restrict__ y,
             int N, float* __restrict__ out) {
    const int tid  = threadIdx.x;
    const int lane = tid & 31;
    const int w    = (blockIdx.x * NTHR + tid) >> 5;
    float* csum = g_csum + (blockIdx.x & (KREP - 1)) * SLAB;

    // per-warp rotated column: warp w's lane handles float4-chunk 'col' and
    // 'col+32'. De-phases the sector order of red bursts across warps.
    const int col = (lane + w) & 31;

    __shared__ int s_hist[C_PAD];
    if (tid < C_PAD) s_hist[tid] = 0;
    __syncthreads();

    // ---- Phase 1: warp w handles rows 2w, 2w+1 ------------------------------
    const int r0 = 2 * w, r1 = 2 * w + 1;
    if (r0 < N) {
        const bool has1 = (r1 < N);
        int c0 = y[r0];
        int c1 = has1 ? y[r1] : -1;

        const float4* e0 = (const float4*)(e + (size_t)r0 * D_DIM);
        const float4* e1 = (const float4*)(e + (size_t)r1 * D_DIM);
        float4 a0 = e0[col];          // same 512B segment as unrotated: coalesced
        float4 b0 = e0[col + 32];
        float4 a1, b1;
        if (has1) { a1 = e1[col]; b1 = e1[col + 32]; }
        else      { a1 = make_float4(0,0,0,0); b1 = a1; }

        float s0 = a0.x*a0.x + a0.y*a0.y + a0.z*a0.z + a0.w*a0.w
                 + b0.x*b0.x + b0.y*b0.y + b0.z*b0.z + b0.w*b0.w;
        float s1 = a1.x*a1.x + a1.y*a1.y + a1.z*a1.z + a1.w*a1.w
                 + b1.x*b1.x + b1.y*b1.y + b1.z*b1.z + b1.w*b1.w;
        #pragma unroll
        for (int o = 16; o > 0; o >>= 1) {
            s0 += __shfl_xor_sync(0xffffffffu, s0, o);
            s1 += __shfl_xor_sync(0xffffffffu, s1, o);
        }
        float q0 = rsqrtf(s0);
        float q1 = rsqrtf(s1);

        if ((unsigned)c0 < C_PAD) {
            float* d0 = csum + c0 * D_DIM + col * 4;
            red_v4(d0,       a0.x*q0, a0.y*q0, a0.z*q0, a0.w*q0);
            red_v4(d0 + 128, b0.x*q0, b0.y*q0, b0.z*q0, b0.w*q0);
            if (lane == 0) atomicAdd(&s_hist[c0], 1);
        }
        if ((unsigned)c1 < C_PAD) {
            float* d1 = csum + c1 * D_DIM + col * 4;
            red_v4(d1,       a1.x*q1, a1.y*q1, a1.z*q1, a1.w*q1);
            red_v4(d1 + 128, b1.x*q1, b1.y*q1, b1.z*q1, b1.w*q1);
            if (lane == 1) atomicAdd(&s_hist[c1], 1);
        }
    }
    __syncthreads();
    if (tid < C_PAD) {
        int h = s_hist[tid];
        if (h) atomicAdd(&g_ccnt[tid], h);
    }

    // ---- Grid spin barrier (all CTAs co-resident: grid <= 128) --------------
    __threadfence();
    __syncthreads();
    if (tid == 0) {
        atomicAdd(&g_bar, 1u);
        unsigned v;
        do {
            asm volatile("ld.acquire.gpu.u32 %0, [%1];" : "=r"(v) : "l"(&g_bar));
        } while (v < gridDim.x);
    }
    __syncthreads();

    // ---- Phase 2: CTA c owns class c ----------------------------------------
    __shared__ float s_S[D_DIM];
    __shared__ float s_part[8];

    for (int c = blockIdx.x; c < C_PAD; c += gridDim.x) {
        float t = 0.0f;
        if (tid < D_DIM) {
            float v0 = __ldcg(&g_csum[0*SLAB + c * D_DIM + tid]);
            float v1 = __ldcg(&g_csum[1*SLAB + c * D_DIM + tid]);
            float v2 = __ldcg(&g_csum[2*SLAB + c * D_DIM + tid]);
            float v3 = __ldcg(&g_csum[3*SLAB + c * D_DIM + tid]);
            t = (v0 + v1) + (v2 + v3);
            s_S[tid] = t;
        }
        float v = t * t;
        #pragma unroll
        for (int o = 16; o > 0; o >>= 1)
            v += __shfl_xor_sync(0xffffffffu, v, o);
        if (tid < D_DIM && lane == 0) s_part[tid >> 5] = v;
        __syncthreads();

        if (tid < 64)   // fold S_c into replicated S_tot
            red_v4(&g_Stot[c & (KREP-1)][tid * 4],
                   s_S[4*tid], s_S[4*tid+1], s_S[4*tid+2], s_S[4*tid+3]);
        if (tid == 0) {
            float ssq = s_part[0] + s_part[1] + s_part[2] + s_part[3]
                      + s_part[4] + s_part[5] + s_part[6] + s_part[7];
            atomicAdd(&g_sumsq[c & (KREP-1)], ssq);
            int n = __ldcg(&g_ccnt[c]);
            atomicAdd(&g_cnt2, n * n);
            g_ccnt[c] = 0;                      // reset for next replay
        }
        if (tid < 64) {
            const float4 z4 = make_float4(0.f,0.f,0.f,0.f);
            ((float4*)(g_csum + 0*SLAB + c * D_DIM))[tid] = z4;
            ((float4*)(g_csum + 1*SLAB + c * D_DIM))[tid] = z4;
            ((float4*)(g_csum + 2*SLAB + c * D_DIM))[tid] = z4;
            ((float4*)(g_csum + 3*SLAB + c * D_DIM))[tid] = z4;
        }
        __syncthreads();
    }

    // ---- Arrive; last CTA finalizes -----------------------------------------
    __shared__ unsigned s_rank;
    __threadfence();
    __syncthreads();
    if (tid == 0) s_rank = atomicAdd(&g_done, 1u);
    __syncthreads();
    if (s_rank != gridDim.x - 1) return;

    float t2 = 0.0f;
    if (tid < D_DIM) {
        float tt = __ldcg(&g_Stot[0][tid]) + __ldcg(&g_Stot[1][tid])
                 + __ldcg(&g_Stot[2][tid]) + __ldcg(&g_Stot[3][tid]);
        t2 = tt * tt;
        g_Stot[0][tid] = 0.f; g_Stot[1][tid] = 0.f;
        g_Stot[2][tid] = 0.f; g_Stot[3][tid] = 0.f;
    }
    #pragma unroll
    for (int o = 16; o > 0; o >>= 1)
        t2 += __shfl_xor_sync(0xffffffffu, t2, o);
    if (tid < D_DIM && lane == 0) s_part[tid >> 5] = t2;
    __syncthreads();

    if (tid == 0) {
        float tot2 = s_part[0] + s_part[1] + s_part[2] + s_part[3]
                   + s_part[4] + s_part[5] + s_part[6] + s_part[7];
        float ssum = __ldcg(&g_sumsq[0]) + __ldcg(&g_sumsq[1])
                   + __ldcg(&g_sumsq[2]) + __ldcg(&g_sumsq[3]);
        double num = (double)tot2 - (double)ssum;
        double den = (double)N * (double)N - (double)__ldcg(&g_cnt2);
        out[0] = (float)(num / den);
        g_sumsq[0] = 0.f; g_sumsq[1] = 0.f; g_sumsq[2] = 0.f; g_sumsq[3] = 0.f;
        g_cnt2 = 0;
        g_bar  = 0;
        g_done = 0;
    }
}

extern "C" void kernel_launch(void* const* d_in, const int* in_sizes, int n_in,
                              void* d_out, int out_size) {
    const float* e   = (const float*)d_in[0];
    const int*   y   = (const int*)d_in[1];
    float*       out = (float*)d_out;
    int N = in_sizes[1];

    // all CTAs co-resident for the spin barrier
    int nblk = (N + 63) / 64;
    if (nblk > 128) nblk = 128;
    if (nblk < 1)   nblk = 1;
    fused_k<<<nblk, NTHR>>>(e, y, N, out);
}